// round 13
// baseline (speedup 1.0000x reference)
#include <cuda_runtime.h>

// out = (Q K^T) V == Q (K^T V).  B=1, H=16, S=4096, D=64, fp32.
// 8x8 register tiles everywhere: 0.5 FFMA2/LDS-byte -> fma-bound, not crossbar.
// Phase A: partial M_hc = K_chunk^T V_chunk   (f32x2, dup-K)
// Phase B: M[h] = sum_c partial               (coalesced + shfl)
// Phase C: out = Q @ M                        (f32x2, dup-Q)

#define NH      16
#define SS      4096
#define DD      64
#define CHUNKS  64          // 64-row chunk per phase-A CTA

__device__ float g_partial[NH * CHUNKS * DD * DD];  // 16.8 MB (L2-resident)
__device__ float g_M[NH * DD * DD];                 // 256 KB, M[h][d*64+j]

// packed fp32x2 FMA: d.lo += a.lo*b.lo ; d.hi += a.hi*b.hi
#define FFMA2(d, a, b) \
    asm("fma.rn.f32x2 %0, %1, %2, %0;" : "+l"(d) : "l"(a), "l"(b))

__device__ __forceinline__ unsigned long long dup2(float f) {
    unsigned long long r;
    asm("mov.b64 %0, {%1, %1};" : "=l"(r) : "f"(f));
    return r;
}

// ---------------------------------------------------------------------------
// Phase A: per-(head, chunk) partial K^T V.
// 64 threads as 8x8; thread (ty,tx) owns M[ty*8..+7][tx*8..+7].
// Per s-step: K 32B (broadcast over tx), V 32B (conflict-free), 32 FFMA2.
// 32 independent accumulators per thread -> single-warp ILP saturates fma.
// ---------------------------------------------------------------------------
__global__ __launch_bounds__(64) void ktv_partial_kernel(
    const float* __restrict__ kg, const float* __restrict__ vg)
{
    __shared__ float ks[DD * DD];   // 16 KB
    __shared__ float vs[DD * DD];   // 16 KB

    const int bx    = blockIdx.x;
    const int h     = bx >> 6;
    const int chunk = bx & 63;
    const int tid   = threadIdx.x;
    const int ty    = tid >> 3;
    const int tx    = tid & 7;

    const float4* Kg = (const float4*)(kg + (h * SS + chunk * 64) * DD);
    const float4* Vg = (const float4*)(vg + (h * SS + chunk * 64) * DD);
    float4* ks4 = (float4*)ks;
    float4* vs4 = (float4*)vs;

    #pragma unroll
    for (int i = 0; i < 16; ++i) {
        int idx = tid + i * 64;
        ks4[idx] = Kg[idx];
        vs4[idx] = Vg[idx];
    }
    __syncthreads();

    unsigned long long acc[8][4];
    #pragma unroll
    for (int r = 0; r < 8; ++r)
        #pragma unroll
        for (int c = 0; c < 4; ++c) acc[r][c] = 0ULL;

    #pragma unroll 8
    for (int s = 0; s < 64; ++s) {
        float4 k0 = *(const float4*)&ks[s * DD + ty * 8];      // broadcast over tx
        float4 k1 = *(const float4*)&ks[s * DD + ty * 8 + 4];
        ulonglong2 v0 = *(const ulonglong2*)&vs[s * DD + tx * 8];     // conflict-free
        ulonglong2 v1 = *(const ulonglong2*)&vs[s * DD + tx * 8 + 4];
        float kf[8] = {k0.x, k0.y, k0.z, k0.w, k1.x, k1.y, k1.z, k1.w};
        #pragma unroll
        for (int r = 0; r < 8; ++r) {
            unsigned long long kd = dup2(kf[r]);
            FFMA2(acc[r][0], kd, v0.x);
            FFMA2(acc[r][1], kd, v0.y);
            FFMA2(acc[r][2], kd, v1.x);
            FFMA2(acc[r][3], kd, v1.y);
        }
    }

    float* P = g_partial + (h * CHUNKS + chunk) * DD * DD;
    #pragma unroll
    for (int r = 0; r < 8; ++r) {
        float* row = &P[(ty * 8 + r) * DD + tx * 8];
        *(ulonglong2*)(row)     = make_ulonglong2(acc[r][0], acc[r][1]);
        *(ulonglong2*)(row + 4) = make_ulonglong2(acc[r][2], acc[r][3]);
    }
}

// ---------------------------------------------------------------------------
// Phase B: reduce 64 chunk-partials per head into M.
// Warp lane layout: lane = (o4 & 3) + 4*p; 4 consecutive float4 outputs and
// 8 chunk-groups per warp -> every load inst covers coalesced 64B segments.
// 3-level shfl combines the 8 chunk-group partials.
// ---------------------------------------------------------------------------
__global__ __launch_bounds__(256) void reduce_kernel()
{
    int t    = blockIdx.x * 256 + threadIdx.x;   // grid 512 -> 131072 threads
    int w    = t >> 5;                           // warp id: owns o4 = 4w..4w+3
    int lane = t & 31;
    int o4   = w * 4 + (lane & 3);               // float4 index into g_M
    int p    = lane >> 2;                        // chunk group 0..7
    int h    = o4 >> 10;
    int e4   = o4 & 1023;

    const float4* P = (const float4*)g_partial + (h * CHUNKS + p * 8) * 1024 + e4;
    float4 s = make_float4(0.f, 0.f, 0.f, 0.f);
    #pragma unroll
    for (int c = 0; c < 8; ++c) {
        float4 q = P[c * 1024];
        s.x += q.x; s.y += q.y; s.z += q.z; s.w += q.w;
    }
    #pragma unroll
    for (int off = 4; off < 32; off <<= 1) {
        s.x += __shfl_xor_sync(0xffffffffu, s.x, off);
        s.y += __shfl_xor_sync(0xffffffffu, s.y, off);
        s.z += __shfl_xor_sync(0xffffffffu, s.z, off);
        s.w += __shfl_xor_sync(0xffffffffu, s.w, off);
    }
    if (p == 0) ((float4*)g_M)[o4] = s;          // lanes 0..3: coalesced 64B
}

// ---------------------------------------------------------------------------
// Phase C: out = Q @ M.  128 threads as 16x8; block covers 128 q-rows x 64
// cols; thread (ty,tx) owns out[ty*8..+7][tx*8..+7].
// Per d-step: Q 8x4B (broadcast over tx, via float4 per 4 steps), M 32B
// conflict-free, 32 FFMA2.
// ---------------------------------------------------------------------------
__global__ __launch_bounds__(128) void qm_kernel(
    const float* __restrict__ qg, float* __restrict__ outg)
{
    __shared__ float qs[128 * DD];  // 32 KB
    __shared__ float ms[DD * DD];   // 16 KB

    const int bx  = blockIdx.x;
    const int h   = bx >> 5;
    const int qt  = bx & 31;        // 32 tiles of 128 rows
    const int tid = threadIdx.x;
    const int ty  = tid >> 3;
    const int tx  = tid & 7;

    const float4* Qg = (const float4*)(qg + (h * SS + qt * 128) * DD);
    const float4* Mg = (const float4*)(g_M + h * 4096);
    float4* qs4 = (float4*)qs;
    float4* ms4 = (float4*)ms;

    #pragma unroll
    for (int i = 0; i < 16; ++i) qs4[tid + i * 128] = Qg[tid + i * 128];
    #pragma unroll
    for (int i = 0; i < 8; ++i)  ms4[tid + i * 128] = Mg[tid + i * 128];
    __syncthreads();

    const int i0 = ty * 8;
    unsigned long long acc[8][4];
    #pragma unroll
    for (int r = 0; r < 8; ++r)
        #pragma unroll
        for (int c = 0; c < 4; ++c) acc[r][c] = 0ULL;

    #pragma unroll 4
    for (int d4 = 0; d4 < 16; ++d4) {
        float4 qv[8];
        #pragma unroll
        for (int r = 0; r < 8; ++r)
            qv[r] = *(const float4*)&qs[(i0 + r) * DD + d4 * 4];   // broadcast
        #pragma unroll
        for (int dd = 0; dd < 4; ++dd) {
            const float* mrow = &ms[(d4 * 4 + dd) * DD + tx * 8];  // conflict-free
            ulonglong2 m0 = *(const ulonglong2*)(mrow);
            ulonglong2 m1 = *(const ulonglong2*)(mrow + 4);
            #pragma unroll
            for (int r = 0; r < 8; ++r) {
                unsigned long long qd = dup2(((const float*)&qv[r])[dd]);
                FFMA2(acc[r][0], qd, m0.x);
                FFMA2(acc[r][1], qd, m0.y);
                FFMA2(acc[r][2], qd, m1.x);
                FFMA2(acc[r][3], qd, m1.y);
            }
        }
    }

    float* O = outg + (h * SS + qt * 128) * DD;
    #pragma unroll
    for (int r = 0; r < 8; ++r) {
        float* row = &O[(i0 + r) * DD + tx * 8];
        *(ulonglong2*)(row)     = make_ulonglong2(acc[r][0], acc[r][1]);
        *(ulonglong2*)(row + 4) = make_ulonglong2(acc[r][2], acc[r][3]);
    }
}

// ---------------------------------------------------------------------------
extern "C" void kernel_launch(void* const* d_in, const int* in_sizes, int n_in,
                              void* d_out, int out_size)
{
    const float* q = (const float*)d_in[0];
    const float* k = (const float*)d_in[1];
    const float* v = (const float*)d_in[2];
    float* out = (float*)d_out;
    (void)in_sizes; (void)n_in; (void)out_size;

    ktv_partial_kernel<<<NH * CHUNKS, 64>>>(k, v);
    reduce_kernel<<<512, 256>>>();
    qm_kernel<<<NH * 32, 128>>>(q, out);
}

// round 14
// speedup vs baseline: 1.1503x; 1.1503x over previous
#include <cuda_runtime.h>
#include <cstdint>

// out = (Q K^T) V == Q (K^T V).  B=1, H=16, S=4096, D=64, fp32.
// R10 shape (256-thr CTAs, 4x4 tiles, f32x2 dup-broadcast) + cp.async
// double-buffered pipelines to overlap GMEM latency with compute.

#define NH      16
#define SS      4096
#define DD      64
#define CHUNKS  32
#define CHUNK_S 128

__device__ float g_partial[NH * CHUNKS * DD * DD];  // 8.4 MB (L2-resident)
__device__ float g_M[NH * DD * DD];                 // 256 KB, M[h][d*64+j]

// packed fp32x2 FMA: d.lo += a.lo*b.lo ; d.hi += a.hi*b.hi
#define FFMA2(d, a, b) \
    asm("fma.rn.f32x2 %0, %1, %2, %0;" : "+l"(d) : "l"(a), "l"(b))

__device__ __forceinline__ unsigned long long dup2(float f) {
    unsigned long long r;
    asm("mov.b64 %0, {%1, %1};" : "=l"(r) : "f"(f));
    return r;
}

#define CP_ASYNC16(dst, src) \
    asm volatile("cp.async.cg.shared.global [%0], [%1], 16;" \
                 :: "r"(dst), "l"(src))
#define CP_COMMIT() asm volatile("cp.async.commit_group;")
#define CP_WAIT1()  asm volatile("cp.async.wait_group 1;")
#define CP_WAIT0()  asm volatile("cp.async.wait_group 0;")

// ---------------------------------------------------------------------------
// Phase A: partial K^T V.  Grid 512 (16 heads x 32 chunks of 128 rows).
// 256 threads as 16x16; thread (ty,tx) owns M[ty*4..+3][tx*4..+3].
// 4 stages of 32 s-rows, double-buffered via cp.async (8 KB K + 8 KB V per
// buffer -> 32 KB smem total, same occupancy as R10).
// ---------------------------------------------------------------------------
__global__ __launch_bounds__(256) void ktv_partial_kernel(
    const float* __restrict__ kg, const float* __restrict__ vg)
{
    __shared__ float ks[2][32 * DD];   // 2 x 8 KB
    __shared__ float vs[2][32 * DD];   // 2 x 8 KB

    const int bx    = blockIdx.x;
    const int h     = bx >> 5;
    const int chunk = bx & 31;
    const int tid   = threadIdx.x;
    const int ty    = tid >> 4;
    const int tx    = tid & 15;

    const float4* Kg = (const float4*)(kg + (h * SS + chunk * CHUNK_S) * DD);
    const float4* Vg = (const float4*)(vg + (h * SS + chunk * CHUNK_S) * DD);
    const uint32_t ksb = (uint32_t)__cvta_generic_to_shared(&ks[0][0]);
    const uint32_t vsb = (uint32_t)__cvta_generic_to_shared(&vs[0][0]);

#define KTV_PREFETCH(st, buf) do {                                      \
        _Pragma("unroll")                                               \
        for (int i = 0; i < 2; ++i) {                                   \
            int idx = tid + i * 256;          /* 512 float4 per stage */\
            CP_ASYNC16(ksb + (buf) * 8192 + idx * 16, Kg + (st) * 512 + idx); \
            CP_ASYNC16(vsb + (buf) * 8192 + idx * 16, Vg + (st) * 512 + idx); \
        }                                                               \
        CP_COMMIT();                                                    \
    } while (0)

    KTV_PREFETCH(0, 0);

    unsigned long long acc[4][2];
    #pragma unroll
    for (int r = 0; r < 4; ++r) { acc[r][0] = 0ULL; acc[r][1] = 0ULL; }

    #pragma unroll
    for (int st = 0; st < 4; ++st) {
        const int cur = st & 1;
        if (st < 3) { KTV_PREFETCH(st + 1, cur ^ 1); CP_WAIT1(); }
        else        { CP_WAIT0(); }
        __syncthreads();

        const float* K = ks[cur];
        const float* V = vs[cur];
        #pragma unroll 8
        for (int s = 0; s < 32; ++s) {
            float4     kk = *(const float4*)&K[s * DD + ty * 4];     // broadcast
            ulonglong2 vv = *(const ulonglong2*)&V[s * DD + tx * 4]; // conflict-free
            unsigned long long kd0 = dup2(kk.x);
            unsigned long long kd1 = dup2(kk.y);
            unsigned long long kd2 = dup2(kk.z);
            unsigned long long kd3 = dup2(kk.w);
            FFMA2(acc[0][0], kd0, vv.x); FFMA2(acc[0][1], kd0, vv.y);
            FFMA2(acc[1][0], kd1, vv.x); FFMA2(acc[1][1], kd1, vv.y);
            FFMA2(acc[2][0], kd2, vv.x); FFMA2(acc[2][1], kd2, vv.y);
            FFMA2(acc[3][0], kd3, vv.x); FFMA2(acc[3][1], kd3, vv.y);
        }
        __syncthreads();   // done reading cur before it is refilled
    }

    float* P = g_partial + (h * CHUNKS + chunk) * DD * DD;
    #pragma unroll
    for (int r = 0; r < 4; ++r) {
        *(ulonglong2*)&P[(ty * 4 + r) * DD + tx * 4] =
            make_ulonglong2(acc[r][0], acc[r][1]);
    }
#undef KTV_PREFETCH
}

// ---------------------------------------------------------------------------
// Phase B: reduce 32 chunk-partials per head into M.  65536 threads, one
// output float each; reads coalesced across threads, MLP 32 via unroll.
// ---------------------------------------------------------------------------
__global__ __launch_bounds__(256) void reduce_kernel()
{
    int o = blockIdx.x * 256 + threadIdx.x;      // grid 256 -> 65536 threads
    int h = o >> 12;
    int e = o & 4095;
    const float* P = g_partial + h * CHUNKS * 4096 + e;
    float sum = 0.f;
    #pragma unroll
    for (int c = 0; c < CHUNKS; ++c) sum += P[c * 4096];
    g_M[o] = sum;
}

// ---------------------------------------------------------------------------
// Phase C: out = Q @ M.  Grid 1024 (16 heads x 64 tiles of 64 q-rows).
// Staged along the reduction dim d: 2 stages of 32, both issued up front via
// cp.async; compute on stage 0 overlaps stage 1's arrival.
// qs[buf][row*32 + dl]  (64 rows x 32 d),  ms[buf][dl*64 + j] (32 d x 64 j).
// ---------------------------------------------------------------------------
__global__ __launch_bounds__(256) void qm_kernel(
    const float* __restrict__ qg, float* __restrict__ outg)
{
    __shared__ float qs[2][64 * 32];   // 2 x 8 KB
    __shared__ float ms[2][32 * 64];   // 2 x 8 KB

    const int bx  = blockIdx.x;
    const int h   = bx >> 6;
    const int qt  = bx & 63;
    const int tid = threadIdx.x;
    const int ty  = tid >> 4;
    const int tx  = tid & 15;

    const float4* Qg = (const float4*)(qg + (h * SS + qt * 64) * DD);
    const float4* Mg = (const float4*)(g_M + h * 4096);
    const uint32_t qsb = (uint32_t)__cvta_generic_to_shared(&qs[0][0]);
    const uint32_t msb = (uint32_t)__cvta_generic_to_shared(&ms[0][0]);

    #pragma unroll
    for (int st = 0; st < 2; ++st) {
        #pragma unroll
        for (int i = 0; i < 2; ++i) {
            int idx = tid + i * 256;             // 512 float4 per stage
            int row = idx >> 3;                  // Q: 8 float4 per row-stage
            int d4  = idx & 7;
            CP_ASYNC16(qsb + st * 8192 + idx * 16, Qg + row * 16 + st * 8 + d4);
            CP_ASYNC16(msb + st * 8192 + idx * 16, Mg + st * 512 + idx);
        }
        CP_COMMIT();
    }

    const int i0 = ty * 4;
    unsigned long long acc[4][2];
    #pragma unroll
    for (int r = 0; r < 4; ++r) { acc[r][0] = 0ULL; acc[r][1] = 0ULL; }

    #pragma unroll
    for (int st = 0; st < 2; ++st) {
        if (st == 0) CP_WAIT1(); else CP_WAIT0();
        __syncthreads();
        const float* Qs = qs[st];
        const float* Ms = ms[st];
        #pragma unroll 4
        for (int d4 = 0; d4 < 8; ++d4) {
            float4 qv[4];
            #pragma unroll
            for (int r = 0; r < 4; ++r)
                qv[r] = *(const float4*)&Qs[(i0 + r) * 32 + d4 * 4]; // broadcast
            #pragma unroll
            for (int dd = 0; dd < 4; ++dd) {
                ulonglong2 mv =
                    *(const ulonglong2*)&Ms[(d4 * 4 + dd) * DD + tx * 4];
                #pragma unroll
                for (int r = 0; r < 4; ++r) {
                    unsigned long long qd = dup2(((const float*)&qv[r])[dd]);
                    FFMA2(acc[r][0], qd, mv.x);
                    FFMA2(acc[r][1], qd, mv.y);
                }
            }
        }
    }

    float* O = outg + (h * SS + qt * 64) * DD;
    #pragma unroll
    for (int r = 0; r < 4; ++r) {
        *(ulonglong2*)&O[(i0 + r) * DD + tx * 4] =
            make_ulonglong2(acc[r][0], acc[r][1]);
    }
}

// ---------------------------------------------------------------------------
extern "C" void kernel_launch(void* const* d_in, const int* in_sizes, int n_in,
                              void* d_out, int out_size)
{
    const float* q = (const float*)d_in[0];
    const float* k = (const float*)d_in[1];
    const float* v = (const float*)d_in[2];
    float* out = (float*)d_out;
    (void)in_sizes; (void)n_in; (void)out_size;

    ktv_partial_kernel<<<NH * CHUNKS, 256>>>(k, v);
    reduce_kernel<<<256, 256>>>();
    qm_kernel<<<NH * 64, 256>>>(q, out);
}

// round 17
// speedup vs baseline: 1.1587x; 1.0073x over previous
#include <cuda_runtime.h>
#include <cstdint>

// out = (Q K^T) V == Q (K^T V).  B=1, H=16, S=4096, D=64, fp32.
// 256-thr CTAs, 4x4 tiles, f32x2 dup-broadcast math, cp.async pipelines.
// R15: ktv grid 1024 (CHUNK_S=64, 4 stages of 16 rows, 16 KB smem).

#define NH      16
#define SS      4096
#define DD      64
#define CHUNKS  64
#define CHUNK_S 64

__device__ float g_partial[NH * CHUNKS * DD * DD];  // 16.8 MB (L2-resident)
__device__ float g_M[NH * DD * DD];                 // 256 KB, M[h][d*64+j]

// packed fp32x2 FMA: d.lo += a.lo*b.lo ; d.hi += a.hi*b.hi
#define FFMA2(d, a, b) \
    asm("fma.rn.f32x2 %0, %1, %2, %0;" : "+l"(d) : "l"(a), "l"(b))

__device__ __forceinline__ unsigned long long dup2(float f) {
    unsigned long long r;
    asm("mov.b64 %0, {%1, %1};" : "=l"(r) : "f"(f));
    return r;
}

#define CP_ASYNC16(dst, src) \
    asm volatile("cp.async.cg.shared.global [%0], [%1], 16;" \
                 :: "r"(dst), "l"(src))
#define CP_COMMIT() asm volatile("cp.async.commit_group;")
#define CP_WAIT1()  asm volatile("cp.async.wait_group 1;")
#define CP_WAIT0()  asm volatile("cp.async.wait_group 0;")

// ---------------------------------------------------------------------------
// Phase A: partial K^T V.  Grid 1024 (16 heads x 64 chunks of 64 rows).
// 256 threads as 16x16; thread (ty,tx) owns M[ty*4..+3][tx*4..+3].
// 4 stages of 16 s-rows, double-buffered cp.async (4 KB per operand-buffer,
// 16 KB smem total) -> ~5 CTAs/SM, ~62% occ.
// ---------------------------------------------------------------------------
__global__ __launch_bounds__(256) void ktv_partial_kernel(
    const float* __restrict__ kg, const float* __restrict__ vg)
{
    __shared__ float ks[2][16 * DD];   // 2 x 4 KB
    __shared__ float vs[2][16 * DD];   // 2 x 4 KB

    const int bx    = blockIdx.x;
    const int h     = bx >> 6;
    const int chunk = bx & 63;
    const int tid   = threadIdx.x;
    const int ty    = tid >> 4;
    const int tx    = tid & 15;

    const float4* Kg = (const float4*)(kg + (h * SS + chunk * CHUNK_S) * DD);
    const float4* Vg = (const float4*)(vg + (h * SS + chunk * CHUNK_S) * DD);
    const uint32_t ksb = (uint32_t)__cvta_generic_to_shared(&ks[0][0]);
    const uint32_t vsb = (uint32_t)__cvta_generic_to_shared(&vs[0][0]);

    // One cp.async per thread per operand per stage (256 float4 = 16 rows).
#define KTV_PREFETCH(st, buf) do {                                       \
        CP_ASYNC16(ksb + (buf) * 4096 + tid * 16, Kg + (st) * 256 + tid); \
        CP_ASYNC16(vsb + (buf) * 4096 + tid * 16, Vg + (st) * 256 + tid); \
        CP_COMMIT();                                                      \
    } while (0)

    KTV_PREFETCH(0, 0);

    unsigned long long acc[4][2];
    #pragma unroll
    for (int r = 0; r < 4; ++r) { acc[r][0] = 0ULL; acc[r][1] = 0ULL; }

    #pragma unroll
    for (int st = 0; st < 4; ++st) {
        const int cur = st & 1;
        if (st < 3) { KTV_PREFETCH(st + 1, cur ^ 1); CP_WAIT1(); }
        else        { CP_WAIT0(); }
        __syncthreads();

        const float* K = ks[cur];
        const float* V = vs[cur];
        #pragma unroll
        for (int s = 0; s < 16; ++s) {
            float4     kk = *(const float4*)&K[s * DD + ty * 4];     // broadcast
            ulonglong2 vv = *(const ulonglong2*)&V[s * DD + tx * 4]; // conflict-free
            unsigned long long kd0 = dup2(kk.x);
            unsigned long long kd1 = dup2(kk.y);
            unsigned long long kd2 = dup2(kk.z);
            unsigned long long kd3 = dup2(kk.w);
            FFMA2(acc[0][0], kd0, vv.x); FFMA2(acc[0][1], kd0, vv.y);
            FFMA2(acc[1][0], kd1, vv.x); FFMA2(acc[1][1], kd1, vv.y);
            FFMA2(acc[2][0], kd2, vv.x); FFMA2(acc[2][1], kd2, vv.y);
            FFMA2(acc[3][0], kd3, vv.x); FFMA2(acc[3][1], kd3, vv.y);
        }
        __syncthreads();   // all reads of cur done before it is refilled
    }

    float* P = g_partial + (h * CHUNKS + chunk) * DD * DD;
    #pragma unroll
    for (int r = 0; r < 4; ++r) {
        *(ulonglong2*)&P[(ty * 4 + r) * DD + tx * 4] =
            make_ulonglong2(acc[r][0], acc[r][1]);
    }
#undef KTV_PREFETCH
}

// ---------------------------------------------------------------------------
// Phase B: reduce 64 chunk-partials per head into M.  65536 threads, one
// output float each; fully coalesced reads, MLP via unroll.
// ---------------------------------------------------------------------------
__global__ __launch_bounds__(256) void reduce_kernel()
{
    int o = blockIdx.x * 256 + threadIdx.x;      // grid 256 -> 65536 threads
    int h = o >> 12;
    int e = o & 4095;
    const float* P = g_partial + h * CHUNKS * 4096 + e;
    float sum = 0.f;
    #pragma unroll
    for (int c = 0; c < CHUNKS; ++c) sum += P[c * 4096];
    g_M[o] = sum;
}

// ---------------------------------------------------------------------------
// Phase C: out = Q @ M.  Grid 1024 (16 heads x 64 tiles of 64 q-rows).
// Staged along d: 2 stages of 32, both issued up front via cp.async.
// qs[buf][row*32 + dl] (64 rows x 32 d), ms[buf][dl*64 + j] (32 d x 64 j).
// ---------------------------------------------------------------------------
__global__ __launch_bounds__(256) void qm_kernel(
    const float* __restrict__ qg, float* __restrict__ outg)
{
    __shared__ float qs[2][64 * 32];   // 2 x 8 KB
    __shared__ float ms[2][32 * 64];   // 2 x 8 KB

    const int bx  = blockIdx.x;
    const int h   = bx >> 6;
    const int qt  = bx & 63;
    const int tid = threadIdx.x;
    const int ty  = tid >> 4;
    const int tx  = tid & 15;

    const float4* Qg = (const float4*)(qg + (h * SS + qt * 64) * DD);
    const float4* Mg = (const float4*)(g_M + h * 4096);
    const uint32_t qsb = (uint32_t)__cvta_generic_to_shared(&qs[0][0]);
    const uint32_t msb = (uint32_t)__cvta_generic_to_shared(&ms[0][0]);

    #pragma unroll
    for (int st = 0; st < 2; ++st) {
        #pragma unroll
        for (int i = 0; i < 2; ++i) {
            int idx = tid + i * 256;             // 512 float4 per stage
            int row = idx >> 3;                  // Q: 8 float4 per row-stage
            int d4  = idx & 7;
            CP_ASYNC16(qsb + st * 8192 + idx * 16, Qg + row * 16 + st * 8 + d4);
            CP_ASYNC16(msb + st * 8192 + idx * 16, Mg + st * 512 + idx);
        }
        CP_COMMIT();
    }

    const int i0 = ty * 4;
    unsigned long long acc[4][2];
    #pragma unroll
    for (int r = 0; r < 4; ++r) { acc[r][0] = 0ULL; acc[r][1] = 0ULL; }

    #pragma unroll
    for (int st = 0; st < 2; ++st) {
        if (st == 0) CP_WAIT1(); else CP_WAIT0();
        __syncthreads();
        const float* Qs = qs[st];
        const float* Ms = ms[st];
        #pragma unroll 4
        for (int d4 = 0; d4 < 8; ++d4) {
            float4 qv[4];
            #pragma unroll
            for (int r = 0; r < 4; ++r)
                qv[r] = *(const float4*)&Qs[(i0 + r) * 32 + d4 * 4]; // broadcast
            #pragma unroll
            for (int dd = 0; dd < 4; ++dd) {
                ulonglong2 mv =
                    *(const ulonglong2*)&Ms[(d4 * 4 + dd) * DD + tx * 4];
                #pragma unroll
                for (int r = 0; r < 4; ++r) {
                    unsigned long long qd = dup2(((const float*)&qv[r])[dd]);
                    FFMA2(acc[r][0], qd, mv.x);
                    FFMA2(acc[r][1], qd, mv.y);
                }
            }
        }
    }

    float* O = outg + (h * SS + qt * 64) * DD;
    #pragma unroll
    for (int r = 0; r < 4; ++r) {
        *(ulonglong2*)&O[(i0 + r) * DD + tx * 4] =
            make_ulonglong2(acc[r][0], acc[r][1]);
    }
}

// ---------------------------------------------------------------------------
extern "C" void kernel_launch(void* const* d_in, const int* in_sizes, int n_in,
                              void* d_out, int out_size)
{
    const float* q = (const float*)d_in[0];
    const float* k = (const float*)d_in[1];
    const float* v = (const float*)d_in[2];
    float* out = (float*)d_out;
    (void)in_sizes; (void)n_in; (void)out_size;

    ktv_partial_kernel<<<NH * CHUNKS, 256>>>(k, v);
    reduce_kernel<<<256, 256>>>();
    qm_kernel<<<NH * 64, 256>>>(q, out);
}